// round 1
// baseline (speedup 1.0000x reference)
#include <cuda_runtime.h>
#include <math.h>

// ---------------- problem constants (fixed shapes) ----------------
#define NB   4            // batch
#define NN   8192         // points per batch
#define CIN  32           // signal channels
#define CF   35           // CIN + 3 edge feats
#define CO   64           // conv output channels
#define KK   32           // neighbors
#define E_TOT (NB*NN*KK)  // 1048576 edges
#define BE   128          // edges per tile
#define NT   (E_TOT/BE)   // 8192 tiles
#define TPB  (NT/NB)      // 2048 tiles per batch
#define MCNT (NN*KK)      // 262144 elements per (b,c) for instance norm

// ---------------- scratch (static __device__, no allocs) ----------------
__device__ float g_bufA[(size_t)NT * CO * BE];   // 268 MB
__device__ float g_bufB[(size_t)NT * CO * BE];   // 268 MB
__device__ float g_psum[CO * NT];
__device__ float g_psq [CO * NT];
__device__ float g_scale[NB * CO];
__device__ float g_shift[NB * CO];
__device__ int   g_e32;

// ---------------- edges dtype detection (int32 vs int64) ----------------
__global__ void detect_kernel(const long long* __restrict__ e)
{
    int f = 0;
    for (int i = 0; i < 64; i++)
        if (((unsigned long long)e[i]) >> 32) f = 1;   // int32 data shows nonzero hi words
    g_e32 = f;
}

// ---------------- layer 1: gather + concat + conv(35->64) + partial stats ----------------
__global__ __launch_bounds__(256) void conv1_kernel(
    const float* __restrict__ signal, const void* __restrict__ edges,
    const float* __restrict__ efeat,  const float* __restrict__ W1)
{
    __shared__ float Xs[CF][BE];   // 17.5 KB
    __shared__ float Ws[CF][CO];   // 8.75 KB
    const int t = threadIdx.x;
    const int tile = blockIdx.x;

    // stage W transposed: Ws[ci][co]
    for (int i = t; i < CF * CO; i += 256) {
        int co = i / CF, ci = i % CF;
        Ws[ci][co] = W1[i];
    }

    // gather: 2 threads per edge, each loads 16 signal floats; thread h==0 adds 3 edge feats
    {
        int el = t >> 1, h = t & 1;
        long long ge = (long long)tile * BE + el;
        long long s;
        if (g_e32) s = ((const int*)edges)[ge];
        else       s = ((const long long*)edges)[ge];
        const float4* row = (const float4*)(signal + s * CIN) + h * 4;
#pragma unroll
        for (int m = 0; m < 4; m++) {
            float4 v = row[m];
            int cb = h * 16 + m * 4;
            Xs[cb + 0][el] = v.x; Xs[cb + 1][el] = v.y;
            Xs[cb + 2][el] = v.z; Xs[cb + 3][el] = v.w;
        }
        if (h == 0) {
            const float* fp = efeat + ge * 3;
            Xs[32][el] = fp[0]; Xs[33][el] = fp[1]; Xs[34][el] = fp[2];
        }
    }
    __syncthreads();

    // register-tiled GEMM: thread = 4 co x 8 e
    const int cg = t & 15, eg = t >> 4;
    const int co0 = cg * 4, e0 = eg * 8;
    float acc[4][8];
#pragma unroll
    for (int j = 0; j < 4; j++)
#pragma unroll
        for (int i = 0; i < 8; i++) acc[j][i] = 0.f;

#pragma unroll 5
    for (int ci = 0; ci < CF; ci++) {
        float4 w  = *(const float4*)&Ws[ci][co0];
        float4 xa = *(const float4*)&Xs[ci][e0];
        float4 xb = *(const float4*)&Xs[ci][e0 + 4];
        float wv[4] = {w.x, w.y, w.z, w.w};
        float xv[8] = {xa.x, xa.y, xa.z, xa.w, xb.x, xb.y, xb.z, xb.w};
#pragma unroll
        for (int j = 0; j < 4; j++)
#pragma unroll
            for (int i = 0; i < 8; i++)
                acc[j][i] = fmaf(wv[j], xv[i], acc[j][i]);
    }

    // per-thread stats
    float s4[4], q4[4];
#pragma unroll
    for (int j = 0; j < 4; j++) {
        float s = 0.f, q = 0.f;
#pragma unroll
        for (int i = 0; i < 8; i++) { s += acc[j][i]; q += acc[j][i] * acc[j][i]; }
        s4[j] = s; q4[j] = q;
    }
    __syncthreads();                 // Xs no longer needed -> overlay reductions
    float* Sred = &Xs[0][0];         // CO*16 floats
    float* Qred = Sred + CO * 16;
#pragma unroll
    for (int j = 0; j < 4; j++) {
        Sred[(co0 + j) * 16 + eg] = s4[j];
        Qred[(co0 + j) * 16 + eg] = q4[j];
    }
    __syncthreads();
    if (t < CO) {
        float S = 0.f, Q = 0.f;
#pragma unroll
        for (int g = 0; g < 16; g++) { S += Sred[t * 16 + g]; Q += Qred[t * 16 + g]; }
        g_psum[t * NT + tile] = S;
        g_psq [t * NT + tile] = Q;
    }

    // write tile in [c][e] layout
    float* dst = g_bufA + (size_t)tile * CO * BE;
#pragma unroll
    for (int j = 0; j < 4; j++)
#pragma unroll
        for (int i = 0; i < 8; i += 4) {
            float4 v = make_float4(acc[j][i], acc[j][i+1], acc[j][i+2], acc[j][i+3]);
            *(float4*)&dst[(co0 + j) * BE + e0 + i] = v;
        }
}

// ---------------- layers 2/3: norm+lrelu (fused in loader) + conv(64->64) + stats ----------------
__global__ __launch_bounds__(256) void conv_mid_kernel(int swap, const float* __restrict__ Wg)
{
    const float* yin  = swap ? g_bufB : g_bufA;
    float*       yout = swap ? g_bufA : g_bufB;
    __shared__ float Xs[CO][BE];   // 32 KB
    __shared__ float Ws[CO][CO];   // 16 KB  (total 48 KB exactly)
    const int t = threadIdx.x;
    const int tile = blockIdx.x;
    const int b = tile / TPB;

    for (int i = t; i < CO * CO; i += 256) {
        int co = i >> 6, ci = i & 63;
        Ws[ci][co] = Wg[i];
    }

    // load tile (same layout) with fused instance-norm + leaky relu
    const float4* src = (const float4*)(yin + (size_t)tile * CO * BE);
    float4* xsv = (float4*)&Xs[0][0];
#pragma unroll
    for (int i = 0; i < 8; i++) {
        int f = i * 256 + t;            // float4 index 0..2047
        int c = f >> 5;                 // 32 float4 per channel row
        float sc = g_scale[b * CO + c];
        float sh = g_shift[b * CO + c];
        float4 v = src[f];
        v.x = fmaf(v.x, sc, sh); v.x = v.x >= 0.f ? v.x : 0.1f * v.x;
        v.y = fmaf(v.y, sc, sh); v.y = v.y >= 0.f ? v.y : 0.1f * v.y;
        v.z = fmaf(v.z, sc, sh); v.z = v.z >= 0.f ? v.z : 0.1f * v.z;
        v.w = fmaf(v.w, sc, sh); v.w = v.w >= 0.f ? v.w : 0.1f * v.w;
        xsv[f] = v;
    }
    __syncthreads();

    const int cg = t & 15, eg = t >> 4;
    const int co0 = cg * 4, e0 = eg * 8;
    float acc[4][8];
#pragma unroll
    for (int j = 0; j < 4; j++)
#pragma unroll
        for (int i = 0; i < 8; i++) acc[j][i] = 0.f;

#pragma unroll 4
    for (int ci = 0; ci < CO; ci++) {
        float4 w  = *(const float4*)&Ws[ci][co0];
        float4 xa = *(const float4*)&Xs[ci][e0];
        float4 xb = *(const float4*)&Xs[ci][e0 + 4];
        float wv[4] = {w.x, w.y, w.z, w.w};
        float xv[8] = {xa.x, xa.y, xa.z, xa.w, xb.x, xb.y, xb.z, xb.w};
#pragma unroll
        for (int j = 0; j < 4; j++)
#pragma unroll
            for (int i = 0; i < 8; i++)
                acc[j][i] = fmaf(wv[j], xv[i], acc[j][i]);
    }

    float s4[4], q4[4];
#pragma unroll
    for (int j = 0; j < 4; j++) {
        float s = 0.f, q = 0.f;
#pragma unroll
        for (int i = 0; i < 8; i++) { s += acc[j][i]; q += acc[j][i] * acc[j][i]; }
        s4[j] = s; q4[j] = q;
    }
    __syncthreads();
    float* Sred = &Xs[0][0];
    float* Qred = Sred + CO * 16;
#pragma unroll
    for (int j = 0; j < 4; j++) {
        Sred[(co0 + j) * 16 + eg] = s4[j];
        Qred[(co0 + j) * 16 + eg] = q4[j];
    }
    __syncthreads();
    if (t < CO) {
        float S = 0.f, Q = 0.f;
#pragma unroll
        for (int g = 0; g < 16; g++) { S += Sred[t * 16 + g]; Q += Qred[t * 16 + g]; }
        g_psum[t * NT + tile] = S;
        g_psq [t * NT + tile] = Q;
    }

    float* dst = yout + (size_t)tile * CO * BE;
#pragma unroll
    for (int j = 0; j < 4; j++)
#pragma unroll
        for (int i = 0; i < 8; i += 4) {
            float4 v = make_float4(acc[j][i], acc[j][i+1], acc[j][i+2], acc[j][i+3]);
            *(float4*)&dst[(co0 + j) * BE + e0 + i] = v;
        }
}

// ---------------- finalize stats -> fused scale/shift ----------------
__global__ void finalize_kernel(const float* __restrict__ gam, const float* __restrict__ bet)
{
    const int b = blockIdx.x >> 6;
    const int c = blockIdx.x & 63;
    __shared__ float sS[256], sQ[256];
    const int t = threadIdx.x;
    float S = 0.f, Q = 0.f;
    const float* ps = g_psum + c * NT + b * TPB;
    const float* pq = g_psq  + c * NT + b * TPB;
    for (int i = t; i < TPB; i += 256) { S += ps[i]; Q += pq[i]; }
    sS[t] = S; sQ[t] = Q;
    __syncthreads();
    for (int off = 128; off > 0; off >>= 1) {
        if (t < off) { sS[t] += sS[t + off]; sQ[t] += sQ[t + off]; }
        __syncthreads();
    }
    if (t == 0) {
        float mu  = sS[0] / (float)MCNT;
        float var = sQ[0] / (float)MCNT - mu * mu;
        float rstd = rsqrtf(var + 1e-5f);
        float scl = gam[c] * rstd;
        g_scale[b * CO + c] = scl;
        g_shift[b * CO + c] = bet[c] - mu * scl;
    }
}

// ---------------- final: norm + lrelu + max over K, write (B,N,CO) ----------------
__global__ __launch_bounds__(256) void pool_kernel(float* __restrict__ out)
{
    const int tile = blockIdx.x;
    const int t = threadIdx.x;
    const int b = tile / TPB;
    const int nloc = t >> 6;      // 4 points per tile
    const int c = t & 63;
    const float sc = g_scale[b * CO + c];
    const float sh = g_shift[b * CO + c];
    const float4* row = (const float4*)(g_bufA + (size_t)tile * CO * BE + c * BE + nloc * KK);
    float m = -1e30f;
#pragma unroll
    for (int i = 0; i < 8; i++) {
        float4 v = row[i];
        float a;
        a = fmaf(v.x, sc, sh); a = a >= 0.f ? a : 0.1f * a; m = fmaxf(m, a);
        a = fmaf(v.y, sc, sh); a = a >= 0.f ? a : 0.1f * a; m = fmaxf(m, a);
        a = fmaf(v.z, sc, sh); a = a >= 0.f ? a : 0.1f * a; m = fmaxf(m, a);
        a = fmaf(v.w, sc, sh); a = a >= 0.f ? a : 0.1f * a; m = fmaxf(m, a);
    }
    const int n = (tile % TPB) * 4 + nloc;
    out[((size_t)b * NN + n) * CO + c] = m;
}

// ---------------- launch ----------------
extern "C" void kernel_launch(void* const* d_in, const int* in_sizes, int n_in,
                              void* d_out, int out_size)
{
    const float* signal = (const float*)d_in[0];
    const void*  edges  = d_in[1];
    const float* efeat  = (const float*)d_in[2];
    // "k" may or may not be materialized as a size-1 input
    const int base = (in_sizes[3] == 1) ? 4 : 3;
    const float* W1 = (const float*)d_in[base + 0];
    const float* g1 = (const float*)d_in[base + 1];
    const float* b1 = (const float*)d_in[base + 2];
    const float* W2 = (const float*)d_in[base + 3];
    const float* g2 = (const float*)d_in[base + 4];
    const float* b2 = (const float*)d_in[base + 5];
    const float* W3 = (const float*)d_in[base + 6];
    const float* g3 = (const float*)d_in[base + 7];
    const float* b3 = (const float*)d_in[base + 8];

    detect_kernel<<<1, 1>>>((const long long*)edges);
    conv1_kernel<<<NT, 256>>>(signal, edges, efeat, W1);
    finalize_kernel<<<NB * CO, 256>>>(g1, b1);
    conv_mid_kernel<<<NT, 256>>>(0, W2);        // A -> B
    finalize_kernel<<<NB * CO, 256>>>(g2, b2);
    conv_mid_kernel<<<NT, 256>>>(1, W3);        // B -> A
    finalize_kernel<<<NB * CO, 256>>>(g3, b3);
    pool_kernel<<<NT, 256>>>((float*)d_out);
}

// round 5
// speedup vs baseline: 1.4253x; 1.4253x over previous
#include <cuda_runtime.h>
#include <math.h>

// ---------------- problem constants ----------------
#define NB   4
#define NN   8192
#define CIN  32
#define CF   35           // CIN + 3
#define CO   64
#define KK   32
#define E_TOT (NB*NN*KK)  // 1048576
#define BE   256          // edges per tile
#define NT   (E_TOT/BE)   // 4096 tiles
#define TPB  (NT/NB)      // 1024 tiles per batch
#define MCNT (NN*KK)

#define CONV1_SMEM (CF*BE*4 + CF*CO*8)               // 35840 + 17920 = 53760
#define CONVM_SMEM (CO*BE*4 + CO*CO*8 + 2*CO*4)      // 65536 + 32768 + 512

// ---------------- scratch ----------------
__device__ float g_bufA[(size_t)NT * CO * BE];
__device__ float g_bufB[(size_t)NT * CO * BE];
__device__ float g_psum[CO * NT];
__device__ float g_psq [CO * NT];
__device__ float g_scale[NB * CO];
__device__ float g_shift[NB * CO];
__device__ int   g_e32;

typedef unsigned long long ull;

__device__ __forceinline__ ull fma2(ull a, ull b, ull c) {
    ull d;
    asm("fma.rn.f32x2 %0, %1, %2, %3;" : "=l"(d) : "l"(a), "l"(b), "l"(c));
    return d;
}
__device__ __forceinline__ float2 up2(ull p) {
    float2 f;
    asm("mov.b64 {%0, %1}, %2;" : "=f"(f.x), "=f"(f.y) : "l"(p));
    return f;
}

// ---------------- edges dtype detection ----------------
__global__ void detect_kernel(const long long* __restrict__ e)
{
    int f = 0;
    for (int i = 0; i < 64; i++)
        if (((unsigned long long)e[i]) >> 32) f = 1;
    g_e32 = f;
}

// ---------------- shared GEMM epilogue: store + partial stats ----------------
__device__ __forceinline__ void gemm_tail(ull acc[8][4], int co0, int l,
                                          float* __restrict__ dst, int tile)
{
#pragma unroll
    for (int j = 0; j < 8; j++) {
        ulonglong2 va; va.x = acc[j][0]; va.y = acc[j][1];
        ulonglong2 vb; vb.x = acc[j][2]; vb.y = acc[j][3];
        *(ulonglong2*)&dst[(co0 + j) * BE + 4 * l]       = va;
        *(ulonglong2*)&dst[(co0 + j) * BE + 128 + 4 * l] = vb;
    }
#pragma unroll
    for (int j = 0; j < 8; j++) {
        float s = 0.f, q = 0.f;
#pragma unroll
        for (int p = 0; p < 4; p++) {
            float2 f = up2(acc[j][p]);
            s += f.x + f.y;
            q += f.x * f.x + f.y * f.y;
        }
#pragma unroll
        for (int o = 16; o; o >>= 1) {
            s += __shfl_xor_sync(0xffffffffu, s, o);
            q += __shfl_xor_sync(0xffffffffu, q, o);
        }
        if (l == 0) {
            g_psum[(co0 + j) * NT + tile] = s;
            g_psq [(co0 + j) * NT + tile] = q;
        }
    }
}

// ---------------- layer 1: gather + concat + conv(35->64) + stats ----------------
__global__ __launch_bounds__(256) void conv1_kernel(
    const float* __restrict__ signal, const void* __restrict__ edges,
    const float* __restrict__ efeat,  const float* __restrict__ W1)
{
    extern __shared__ char dynsmem[];
    float*  Xs  = (float*)dynsmem;                    // [CF][BE]
    float2* Ws2 = (float2*)(dynsmem + CF * BE * 4);   // [CF][CO] duplicated pairs

    const int t = threadIdx.x;
    const int tile = blockIdx.x;

    // stage weights duplicated: Ws2[ci][co] = (w, w)
    for (int i = t; i < CF * CO; i += 256) {
        int ci = i >> 6, co = i & 63;
        float w = W1[co * CF + ci];
        Ws2[ci * CO + co] = make_float2(w, w);
    }

    // gather: 1 thread per edge
    {
        long long ge = (long long)tile * BE + t;
        long long s = g_e32 ? (long long)((const int*)edges)[ge]
                            : ((const long long*)edges)[ge];
        const float4* row = (const float4*)(signal + s * CIN);
#pragma unroll
        for (int m = 0; m < 8; m++) {
            float4 v = row[m];
            int cb = m * 4;
            Xs[(cb + 0) * BE + t] = v.x; Xs[(cb + 1) * BE + t] = v.y;
            Xs[(cb + 2) * BE + t] = v.z; Xs[(cb + 3) * BE + t] = v.w;
        }
        const float* fp = efeat + ge * 3;
        Xs[32 * BE + t] = fp[0];
        Xs[33 * BE + t] = fp[1];
        Xs[34 * BE + t] = fp[2];
    }
    __syncthreads();

    const int w = t >> 5, l = t & 31;
    const int co0 = w * 8;

    ull acc[8][4];
#pragma unroll
    for (int j = 0; j < 8; j++)
#pragma unroll
        for (int q = 0; q < 4; q++) acc[j][q] = 0ULL;

#pragma unroll 5
    for (int ci = 0; ci < CF; ci++) {
        const float* xrow = Xs + ci * BE;
        ulonglong2 xa = *(const ulonglong2*)(xrow + 4 * l);
        ulonglong2 xb = *(const ulonglong2*)(xrow + 128 + 4 * l);
        const ulonglong2* wrow = (const ulonglong2*)(Ws2 + ci * CO + co0);
        ulonglong2 w0 = wrow[0], w1 = wrow[1], w2 = wrow[2], w3 = wrow[3];
        ull wp[8] = {w0.x, w0.y, w1.x, w1.y, w2.x, w2.y, w3.x, w3.y};
        ull xp[4] = {xa.x, xa.y, xb.x, xb.y};
#pragma unroll
        for (int j = 0; j < 8; j++)
#pragma unroll
            for (int q = 0; q < 4; q++)
                acc[j][q] = fma2(wp[j], xp[q], acc[j][q]);
    }

    gemm_tail(acc, co0, l, g_bufA + (size_t)tile * CO * BE, tile);
}

// ---------------- layers 2/3: fused norm+lrelu loader + conv(64->64) + stats ----------------
__global__ __launch_bounds__(256) void conv_mid_kernel(int swap, const float* __restrict__ Wg)
{
    const float* yin  = swap ? g_bufB : g_bufA;
    float*       yout = swap ? g_bufA : g_bufB;

    extern __shared__ char dynsmem[];
    float*  Xs   = (float*)dynsmem;                              // [CO][BE]
    float2* Ws2  = (float2*)(dynsmem + CO * BE * 4);             // [CO][CO] dup pairs
    float*  s_sc = (float*)(dynsmem + CO * BE * 4 + CO * CO * 8);
    float*  s_sh = s_sc + CO;

    const int t = threadIdx.x;
    const int tile = blockIdx.x;
    const int b = tile / TPB;

    for (int i = t; i < CO * CO; i += 256) {
        int ci = i >> 6, co = i & 63;
        float w = Wg[co * CO + ci];
        Ws2[ci * CO + co] = make_float2(w, w);
    }
    if (t < CO) {
        s_sc[t] = g_scale[b * CO + t];
        s_sh[t] = g_shift[b * CO + t];
    }
    __syncthreads();

    // load tile with fused instance-norm + leaky relu
    const float4* src = (const float4*)(yin + (size_t)tile * CO * BE);
    float4* xsv = (float4*)Xs;
#pragma unroll
    for (int i = 0; i < 16; i++) {
        int f = i * 256 + t;          // float4 index 0..4095
        int c = f >> 6;               // 64 float4 per channel row
        float sc = s_sc[c], sh = s_sh[c];
        float4 v = src[f];
        v.x = fmaf(v.x, sc, sh); v.x = v.x >= 0.f ? v.x : 0.1f * v.x;
        v.y = fmaf(v.y, sc, sh); v.y = v.y >= 0.f ? v.y : 0.1f * v.y;
        v.z = fmaf(v.z, sc, sh); v.z = v.z >= 0.f ? v.z : 0.1f * v.z;
        v.w = fmaf(v.w, sc, sh); v.w = v.w >= 0.f ? v.w : 0.1f * v.w;
        xsv[f] = v;
    }
    __syncthreads();

    const int w = t >> 5, l = t & 31;
    const int co0 = w * 8;

    ull acc[8][4];
#pragma unroll
    for (int j = 0; j < 8; j++)
#pragma unroll
        for (int q = 0; q < 4; q++) acc[j][q] = 0ULL;

#pragma unroll 4
    for (int ci = 0; ci < CO; ci++) {
        const float* xrow = Xs + ci * BE;
        ulonglong2 xa = *(const ulonglong2*)(xrow + 4 * l);
        ulonglong2 xb = *(const ulonglong2*)(xrow + 128 + 4 * l);
        const ulonglong2* wrow = (const ulonglong2*)(Ws2 + ci * CO + co0);
        ulonglong2 w0 = wrow[0], w1 = wrow[1], w2 = wrow[2], w3 = wrow[3];
        ull wp[8] = {w0.x, w0.y, w1.x, w1.y, w2.x, w2.y, w3.x, w3.y};
        ull xp[4] = {xa.x, xa.y, xb.x, xb.y};
#pragma unroll
        for (int j = 0; j < 8; j++)
#pragma unroll
            for (int q = 0; q < 4; q++)
                acc[j][q] = fma2(wp[j], xp[q], acc[j][q]);
    }

    gemm_tail(acc, co0, l, yout + (size_t)tile * CO * BE, tile);
}

// ---------------- finalize stats -> fused scale/shift ----------------
__global__ void finalize_kernel(const float* __restrict__ gam, const float* __restrict__ bet)
{
    const int b = blockIdx.x >> 6;
    const int c = blockIdx.x & 63;
    __shared__ float sS[256], sQ[256];
    const int t = threadIdx.x;
    float S = 0.f, Q = 0.f;
    const float* ps = g_psum + c * NT + b * TPB;
    const float* pq = g_psq  + c * NT + b * TPB;
    for (int i = t; i < TPB; i += 256) { S += ps[i]; Q += pq[i]; }
    sS[t] = S; sQ[t] = Q;
    __syncthreads();
    for (int off = 128; off > 0; off >>= 1) {
        if (t < off) { sS[t] += sS[t + off]; sQ[t] += sQ[t + off]; }
        __syncthreads();
    }
    if (t == 0) {
        float mu  = sS[0] / (float)MCNT;
        float var = sQ[0] / (float)MCNT - mu * mu;
        float rstd = rsqrtf(var + 1e-5f);
        float scl = gam[c] * rstd;
        g_scale[b * CO + c] = scl;
        g_shift[b * CO + c] = bet[c] - mu * scl;
    }
}

// ---------------- final: norm + lrelu + max over K ----------------
__global__ __launch_bounds__(256) void pool_kernel(float* __restrict__ out)
{
    __shared__ float s_sc[CO], s_sh[CO];
    __shared__ float s_out[8 * CO];
    const int t = threadIdx.x;
    const int tile = blockIdx.x;
    const int b = tile / TPB;

    if (t < CO) {
        s_sc[t] = g_scale[b * CO + t];
        s_sh[t] = g_shift[b * CO + t];
    }
    __syncthreads();

    const int p = t >> 5;         // point within tile (8 points of 32 neighbors)
    const int l = t & 31;
    const int coff = l >> 3;      // 4 channels per iteration chunk
    const int kk = l & 7;         // 8 lanes cover 32 k via float4

    const float* base = g_bufA + (size_t)tile * CO * BE + p * KK;
#pragma unroll
    for (int c0 = 0; c0 < CO; c0 += 4) {
        int c = c0 + coff;
        float sc = s_sc[c], sh = s_sh[c];
        float4 v = *(const float4*)(base + c * BE + kk * 4);
        float a, m = -1e30f;
        a = fmaf(v.x, sc, sh); a = a >= 0.f ? a : 0.1f * a; m = fmaxf(m, a);
        a = fmaf(v.y, sc, sh); a = a >= 0.f ? a : 0.1f * a; m = fmaxf(m, a);
        a = fmaf(v.z, sc, sh); a = a >= 0.f ? a : 0.1f * a; m = fmaxf(m, a);
        a = fmaf(v.w, sc, sh); a = a >= 0.f ? a : 0.1f * a; m = fmaxf(m, a);
        m = fmaxf(m, __shfl_xor_sync(0xffffffffu, m, 1));
        m = fmaxf(m, __shfl_xor_sync(0xffffffffu, m, 2));
        m = fmaxf(m, __shfl_xor_sync(0xffffffffu, m, 4));
        if (kk == 0) s_out[p * CO + c] = m;
    }
    __syncthreads();

    // block-contiguous store: 8 points x 64 channels = 512 floats = 128 float4
    float4* o4 = (float4*)(out + ((size_t)b * NN + (size_t)(tile % TPB) * 8) * CO);
    const float4* s4 = (const float4*)s_out;
    if (t < 128) o4[t] = s4[t];
}

// ---------------- launch ----------------
extern "C" void kernel_launch(void* const* d_in, const int* in_sizes, int n_in,
                              void* d_out, int out_size)
{
    const float* signal = (const float*)d_in[0];
    const void*  edges  = d_in[1];
    const float* efeat  = (const float*)d_in[2];
    const int base = (in_sizes[3] == 1) ? 4 : 3;
    const float* W1 = (const float*)d_in[base + 0];
    const float* g1 = (const float*)d_in[base + 1];
    const float* b1 = (const float*)d_in[base + 2];
    const float* W2 = (const float*)d_in[base + 3];
    const float* g2 = (const float*)d_in[base + 4];
    const float* b2 = (const float*)d_in[base + 5];
    const float* W3 = (const float*)d_in[base + 6];
    const float* g3 = (const float*)d_in[base + 7];
    const float* b3 = (const float*)d_in[base + 8];

    cudaFuncSetAttribute(conv1_kernel, cudaFuncAttributeMaxDynamicSharedMemorySize, CONV1_SMEM);
    cudaFuncSetAttribute(conv_mid_kernel, cudaFuncAttributeMaxDynamicSharedMemorySize, CONVM_SMEM);

    detect_kernel<<<1, 1>>>((const long long*)edges);
    conv1_kernel<<<NT, 256, CONV1_SMEM>>>(signal, edges, efeat, W1);
    finalize_kernel<<<NB * CO, 256>>>(g1, b1);
    conv_mid_kernel<<<NT, 256, CONVM_SMEM>>>(0, W2);   // A -> B
    finalize_kernel<<<NB * CO, 256>>>(g2, b2);
    conv_mid_kernel<<<NT, 256, CONVM_SMEM>>>(1, W3);   // B -> A
    finalize_kernel<<<NB * CO, 256>>>(g3, b3);
    pool_kernel<<<NT, 256>>>((float*)d_out);
}

// round 7
// speedup vs baseline: 1.6918x; 1.1870x over previous
#include <cuda_runtime.h>
#include <cstdint>
#include <math.h>

// ---------------- problem constants ----------------
#define NB    4
#define NN    8192
#define CO    64
#define KKN   32
#define E_TOT (NB*NN*KKN)     // 1048576
#define TE    256             // edges per tile
#define NTIL  (E_TOT/TE)      // 4096
#define TPBt  (NTIL/NB)       // 1024
#define TPC   2
#define GRIDC (NTIL/TPC)      // 2048
#define NPTS  (E_TOT/KKN)     // 32768
#define MCNT  (NN*KKN)

#define SEGB  528             // padded A-frag segment stride (33 float4)
#define KS1   5               // conv1 k-steps (35 -> 40)
#define KSM   8               // mid k-steps (64)

#define AF1_B (16*KS1*SEGB)               // 42240
#define WF1_B (KS1*8*32*16)               // 20480
#define SM1_TOT (AF1_B + WF1_B)           // 62720
#define AFM_B (16*KSM*SEGB)               // 67584
#define WFM_B (KSM*8*32*16)               // 32768
#define SMM_TOT (AFM_B + WFM_B + 512)     // 100864 -> 2 CTA/SM

// ---------------- device scratch ----------------
__device__ float g_bufA[(size_t)E_TOT * CO];   // 268 MB
__device__ float g_bufB[(size_t)E_TOT * CO];   // 268 MB
__device__ float g_psum[(size_t)NTIL * 8 * CO];
__device__ float g_psq [(size_t)NTIL * 8 * CO];
__device__ float g_mx  [(size_t)NPTS * CO];
__device__ float g_mn  [(size_t)NPTS * CO];
__device__ float g_scale[NB * CO];
__device__ float g_shift[NB * CO];
__device__ int   g_e32;

// ---------------- tf32 helpers ----------------
__device__ __forceinline__ uint32_t tf32hi(float x) {
    uint32_t u;
    asm("cvt.rna.tf32.f32 %0, %1;" : "=r"(u) : "f"(x));
    return u;
}
__device__ __forceinline__ void split(float x, uint32_t& h, uint32_t& lo) {
    h = tf32hi(x);
    lo = tf32hi(x - __uint_as_float(h));
}
__device__ __forceinline__ void mma8(float* d, const uint32_t* a, uint32_t b0, uint32_t b1) {
    asm volatile("mma.sync.aligned.m16n8k8.row.col.f32.tf32.tf32.f32 "
        "{%0,%1,%2,%3}, {%4,%5,%6,%7}, {%8,%9}, {%0,%1,%2,%3};"
        : "+f"(d[0]), "+f"(d[1]), "+f"(d[2]), "+f"(d[3])
        : "r"(a[0]), "r"(a[1]), "r"(a[2]), "r"(a[3]), "r"(b0), "r"(b1));
}

// A-fragment scatter store: element (e, c) of the tile
template<int KSTEPS>
__device__ __forceinline__ void af_store(char* AF, int e, int c, float v) {
    int ks = c >> 3, cc = c & 7;
    int lane = ((e & 7) << 2) + (cc & 3);
    int slot = ((e >> 3) & 1) | (((cc >> 2) & 1) << 1);
    *(float*)(AF + ((e >> 4) * KSTEPS + ks) * SEGB + lane * 16 + slot * 4) = v;
}

// W fragments: packed (bh0, bh1, bl0, bl1) per (kstep, ntile, lane)
__device__ __forceinline__ void build_wfrag(char* WF, const float* __restrict__ Wg,
                                            int CI, int KSTEPS, int KVALID, int t) {
    for (int i = t; i < KSTEPS * 8 * 32; i += 256) {
        int lane = i & 31, nt = (i >> 5) & 7, ks = i >> 8;
        int g = lane >> 2, tg = lane & 3;
        int co = nt * 8 + g;
        int k0 = ks * 8 + tg, k1 = k0 + 4;
        float w0 = (k0 < KVALID) ? Wg[co * CI + k0] : 0.f;
        float w1 = (k1 < KVALID) ? Wg[co * CI + k1] : 0.f;
        uint32_t h0, l0, h1, l1;
        split(w0, h0, l0); split(w1, h1, l1);
        *(float4*)(WF + (size_t)i * 16) =
            make_float4(__uint_as_float(h0), __uint_as_float(h1),
                        __uint_as_float(l0), __uint_as_float(l1));
    }
}

// ---------------- GEMM: warp = m32 x n64, 3xTF32 ----------------
template<int KSTEPS>
__device__ __forceinline__ void gemm_tile(const char* AF, const char* WF,
                                          int w, int l, float acc[2][8][4]) {
#pragma unroll
    for (int mt = 0; mt < 2; mt++)
#pragma unroll
        for (int nt = 0; nt < 8; nt++)
#pragma unroll
            for (int q = 0; q < 4; q++) acc[mt][nt][q] = 0.f;

#pragma unroll
    for (int ks = 0; ks < KSTEPS; ks++) {
        float4 x0 = *(const float4*)(AF + ((2 * w)     * KSTEPS + ks) * SEGB + l * 16);
        float4 x1 = *(const float4*)(AF + ((2 * w + 1) * KSTEPS + ks) * SEGB + l * 16);
        uint32_t ah0[4], al0[4], ah1[4], al1[4];
        split(x0.x, ah0[0], al0[0]); split(x0.y, ah0[1], al0[1]);
        split(x0.z, ah0[2], al0[2]); split(x0.w, ah0[3], al0[3]);
        split(x1.x, ah1[0], al1[0]); split(x1.y, ah1[1], al1[1]);
        split(x1.z, ah1[2], al1[2]); split(x1.w, ah1[3], al1[3]);
#pragma unroll
        for (int nt = 0; nt < 8; nt++) {
            float4 bv = *(const float4*)(WF + ((ks * 8 + nt) * 32 + l) * 16);
            uint32_t bh0 = __float_as_uint(bv.x), bh1 = __float_as_uint(bv.y);
            uint32_t bl0 = __float_as_uint(bv.z), bl1 = __float_as_uint(bv.w);
            mma8(acc[0][nt], ah0, bh0, bh1);
            mma8(acc[0][nt], al0, bh0, bh1);
            mma8(acc[0][nt], ah0, bl0, bl1);
            mma8(acc[1][nt], ah1, bh0, bh1);
            mma8(acc[1][nt], al1, bh0, bh1);
            mma8(acc[1][nt], ah1, bl0, bl1);
        }
    }
}

// ---------------- epilogues ----------------
__device__ __forceinline__ void epi_store(float acc[2][8][4], float* __restrict__ yout,
                                          int tile, int w, int l) {
    float* base = yout + ((size_t)tile * TE + w * 32) * CO;
    int r = l >> 2, j2 = (l & 3) * 2;
#pragma unroll
    for (int mt = 0; mt < 2; mt++)
#pragma unroll
        for (int nt = 0; nt < 8; nt++) {
            int c = nt * 8 + j2;
            *(float2*)&base[(mt * 16 + r)     * CO + c] = make_float2(acc[mt][nt][0], acc[mt][nt][1]);
            *(float2*)&base[(mt * 16 + r + 8) * CO + c] = make_float2(acc[mt][nt][2], acc[mt][nt][3]);
        }
}

__device__ __forceinline__ void epi_stats(float acc[2][8][4], int tile, int w, int l, bool domm) {
#pragma unroll
    for (int nt = 0; nt < 8; nt++)
#pragma unroll
        for (int p = 0; p < 2; p++) {
            float s = 0.f, q = 0.f, mx = -1e30f, mn = 1e30f;
#pragma unroll
            for (int mt = 0; mt < 2; mt++)
#pragma unroll
                for (int hh = 0; hh < 2; hh++) {
                    float v = acc[mt][nt][hh * 2 + p];
                    s += v; q += v * v;
                    mx = fmaxf(mx, v); mn = fminf(mn, v);
                }
#pragma unroll
            for (int o = 4; o <= 16; o <<= 1) {
                s += __shfl_xor_sync(0xffffffffu, s, o);
                q += __shfl_xor_sync(0xffffffffu, q, o);
                if (domm) {
                    mx = fmaxf(mx, __shfl_xor_sync(0xffffffffu, mx, o));
                    mn = fminf(mn, __shfl_xor_sync(0xffffffffu, mn, o));
                }
            }
            if (l < 4) {
                int c = nt * 8 + l * 2 + p;
                size_t slot = (size_t)tile * 8 + w;
                g_psum[slot * CO + c] = s;
                g_psq [slot * CO + c] = q;
                if (domm) {
                    g_mx[slot * CO + c] = mx;   // slot == point index
                    g_mn[slot * CO + c] = mn;
                }
            }
        }
}

// ---------------- edges dtype detection ----------------
__global__ void detect_kernel(const long long* __restrict__ e)
{
    int f = 0;
    for (int i = 0; i < 64; i++)
        if (((unsigned long long)e[i]) >> 32) f = 1;
    g_e32 = f;
}

// ---------------- layer 1: gather + concat + GEMM(K=40) ----------------
__global__ __launch_bounds__(256, 2) void conv1_kernel(
    const float* __restrict__ signal, const void* __restrict__ edges,
    const float* __restrict__ efeat,  const float* __restrict__ W1)
{
    extern __shared__ char sm[];
    char* AF = sm;
    char* WF = sm + AF1_B;
    const int t = threadIdx.x, w = t >> 5, l = t & 31;
    const int e32 = g_e32;

    build_wfrag(WF, W1, 35, KS1, 35, t);
    __syncthreads();

    for (int it = 0; it < TPC; it++) {
        const int tile = blockIdx.x * TPC + it;
        {
            long long ge = (long long)tile * TE + t;
            long long s = e32 ? (long long)((const int*)edges)[ge]
                              : ((const long long*)edges)[ge];
            const float4* row = (const float4*)(signal + s * 32);
#pragma unroll
            for (int m = 0; m < 8; m++) {
                float4 v = row[m];
                af_store<KS1>(AF, t, 4 * m + 0, v.x);
                af_store<KS1>(AF, t, 4 * m + 1, v.y);
                af_store<KS1>(AF, t, 4 * m + 2, v.z);
                af_store<KS1>(AF, t, 4 * m + 3, v.w);
            }
            const float* fp = efeat + ge * 3;
            af_store<KS1>(AF, t, 32, fp[0]);
            af_store<KS1>(AF, t, 33, fp[1]);
            af_store<KS1>(AF, t, 34, fp[2]);
#pragma unroll
            for (int c = 35; c < 40; c++) af_store<KS1>(AF, t, c, 0.f);
        }
        __syncthreads();

        float acc[2][8][4];
        gemm_tile<KS1>(AF, WF, w, l, acc);
        epi_store(acc, g_bufA, tile, w, l);
        epi_stats(acc, tile, w, l, false);
        __syncthreads();
    }
}

// ---------------- layers 2/3: fused norm+lrelu + GEMM(K=64) ----------------
__global__ __launch_bounds__(256, 2) void conv_mid_kernel(int swap, const float* __restrict__ Wg, int mode)
{
    const float* __restrict__ yin = swap ? g_bufB : g_bufA;
    float* __restrict__ yout      = swap ? g_bufA : g_bufB;

    extern __shared__ char sm[];
    char* AF = sm;
    char* WF = sm + AFM_B;
    float* s_sc = (float*)(sm + AFM_B + WFM_B);
    float* s_sh = s_sc + CO;
    const int t = threadIdx.x, w = t >> 5, l = t & 31;
    const int b = (blockIdx.x * TPC) / TPBt;

    build_wfrag(WF, Wg, 64, KSM, 64, t);
    if (t < CO) {
        s_sc[t] = g_scale[b * CO + t];
        s_sh[t] = g_shift[b * CO + t];
    }
    __syncthreads();

    for (int it = 0; it < TPC; it++) {
        const int tile = blockIdx.x * TPC + it;
        const float4* src = (const float4*)(yin + (size_t)tile * TE * CO);
#pragma unroll
        for (int i = 0; i < 16; i++) {
            int f = i * 256 + t;
            float4 v = src[f];
            int e = f >> 4, c0 = (f & 15) * 4;
            float y;
            y = fmaf(v.x, s_sc[c0 + 0], s_sh[c0 + 0]); y = y >= 0.f ? y : 0.1f * y;
            af_store<KSM>(AF, e, c0 + 0, y);
            y = fmaf(v.y, s_sc[c0 + 1], s_sh[c0 + 1]); y = y >= 0.f ? y : 0.1f * y;
            af_store<KSM>(AF, e, c0 + 1, y);
            y = fmaf(v.z, s_sc[c0 + 2], s_sh[c0 + 2]); y = y >= 0.f ? y : 0.1f * y;
            af_store<KSM>(AF, e, c0 + 2, y);
            y = fmaf(v.w, s_sc[c0 + 3], s_sh[c0 + 3]); y = y >= 0.f ? y : 0.1f * y;
            af_store<KSM>(AF, e, c0 + 3, y);
        }
        __syncthreads();

        float acc[2][8][4];
        gemm_tile<KSM>(AF, WF, w, l, acc);
        if (mode == 0) {
            epi_store(acc, yout, tile, w, l);
            epi_stats(acc, tile, w, l, false);
        } else {
            epi_stats(acc, tile, w, l, true);
        }
        __syncthreads();
    }
}

// ---------------- finalize stats -> fused scale/shift ----------------
__global__ void finalize_kernel(const float* __restrict__ gam, const float* __restrict__ bet)
{
    const int b = blockIdx.x >> 6;
    const int c = blockIdx.x & 63;
    __shared__ float sS[256], sQ[256];
    const int t = threadIdx.x;
    float S = 0.f, Q = 0.f;
    const size_t base = (size_t)b * (TPBt * 8);
    for (int i = t; i < TPBt * 8; i += 256) {
        S += g_psum[(base + i) * CO + c];
        Q += g_psq [(base + i) * CO + c];
    }
    sS[t] = S; sQ[t] = Q;
    __syncthreads();
    for (int off = 128; off > 0; off >>= 1) {
        if (t < off) { sS[t] += sS[t + off]; sQ[t] += sQ[t + off]; }
        __syncthreads();
    }
    if (t == 0) {
        float mu  = sS[0] / (float)MCNT;
        float var = sQ[0] / (float)MCNT - mu * mu;
        float rstd = rsqrtf(var + 1e-5f);
        float scl = gam[c] * rstd;
        g_scale[b * CO + c] = scl;
        g_shift[b * CO + c] = bet[c] - mu * scl;
    }
}

// ---------------- final pool: affine + lrelu on max/min ----------------
__global__ __launch_bounds__(256) void pool_kernel(float* __restrict__ out)
{
    const int i = blockIdx.x * 256 + threadIdx.x;   // point*64 + c
    const int p = i >> 6, c = i & 63;
    const int b = p >> 13;
    const float sc = g_scale[b * CO + c];
    const float sh = g_shift[b * CO + c];
    const float v = (sc >= 0.f) ? g_mx[i] : g_mn[i];
    float y = fmaf(v, sc, sh);
    out[i] = y >= 0.f ? y : 0.1f * y;
}

// ---------------- launch ----------------
extern "C" void kernel_launch(void* const* d_in, const int* in_sizes, int n_in,
                              void* d_out, int out_size)
{
    const float* signal = (const float*)d_in[0];
    const void*  edges  = d_in[1];
    const float* efeat  = (const float*)d_in[2];
    const int base = (in_sizes[3] == 1) ? 4 : 3;
    const float* W1 = (const float*)d_in[base + 0];
    const float* g1 = (const float*)d_in[base + 1];
    const float* b1 = (const float*)d_in[base + 2];
    const float* W2 = (const float*)d_in[base + 3];
    const float* g2 = (const float*)d_in[base + 4];
    const float* b2 = (const float*)d_in[base + 5];
    const float* W3 = (const float*)d_in[base + 6];
    const float* g3 = (const float*)d_in[base + 7];
    const float* b3 = (const float*)d_in[base + 8];

    cudaFuncSetAttribute(conv1_kernel,    cudaFuncAttributeMaxDynamicSharedMemorySize, SM1_TOT);
    cudaFuncSetAttribute(conv_mid_kernel, cudaFuncAttributeMaxDynamicSharedMemorySize, SMM_TOT);

    detect_kernel<<<1, 1>>>((const long long*)edges);
    conv1_kernel<<<GRIDC, 256, SM1_TOT>>>(signal, edges, efeat, W1);
    finalize_kernel<<<NB * CO, 256>>>(g1, b1);
    conv_mid_kernel<<<GRIDC, 256, SMM_TOT>>>(0, W2, 0);   // A -> B
    finalize_kernel<<<NB * CO, 256>>>(g2, b2);
    conv_mid_kernel<<<GRIDC, 256, SMM_TOT>>>(1, W3, 1);   // B -> max/min
    finalize_kernel<<<NB * CO, 256>>>(g3, b3);
    pool_kernel<<<NPTS * CO / 256, 256>>>((float*)d_out);
}

// round 11
// speedup vs baseline: 2.2208x; 1.3127x over previous
#include <cuda_runtime.h>
#include <cuda_bf16.h>
#include <cstdint>
#include <math.h>

// ---------------- problem constants ----------------
#define NB    4
#define NN    8192
#define CO    64
#define KKN   32
#define E_TOT (NB*NN*KKN)     // 1048576
#define TE    256             // edges per tile
#define NTIL  (E_TOT/TE)      // 4096
#define TPBt  (NTIL/NB)       // 1024
#define TPC   2
#define GRIDC (NTIL/TPC)      // 2048
#define NPTS  (E_TOT/KKN)     // 32768
#define MCNT  (NN*KKN)

#define SEGSZ 1040            // padded A-frag segment (512 hi + 512 lo + 16 pad)
#define KS1   3               // conv1 k16-steps (35 -> 48)
#define KSM   4               // mid k16-steps (64)

#define AF1_B (16*KS1*SEGSZ)              // 49920
#define WF1_B (KS1*8*32*16)               // 12288
#define SM1_TOT (AF1_B + WF1_B)           // 62208
#define AFM_B (16*KSM*SEGSZ)              // 66560
#define WFM_B (KSM*8*32*16)               // 16384
#define SMM_TOT (AFM_B + WFM_B + 512)     // 83456 -> 2 CTA/SM

// ---------------- device scratch ----------------
__device__ float g_bufA[(size_t)E_TOT * CO];   // 268 MB
__device__ float g_bufB[(size_t)E_TOT * CO];   // 268 MB
__device__ float g_psum[(size_t)NTIL * 8 * CO];
__device__ float g_psq [(size_t)NTIL * 8 * CO];
__device__ float g_mx  [(size_t)NPTS * CO];
__device__ float g_mn  [(size_t)NPTS * CO];
__device__ float g_scale[NB * CO];
__device__ float g_shift[NB * CO];
__device__ int   g_e32;

// ---------------- bf16 helpers ----------------
// pack: low half = lo_val, high half = hi_val
__device__ __forceinline__ uint32_t cvt2(float hi_val, float lo_val) {
    uint32_t r;
    asm("cvt.rn.bf16x2.f32 %0, %1, %2;" : "=r"(r) : "f"(hi_val), "f"(lo_val));
    return r;
}
__device__ __forceinline__ float blo(uint32_t p) { return __uint_as_float(p << 16); }
__device__ __forceinline__ float bhi(uint32_t p) { return __uint_as_float(p & 0xffff0000u); }

// split pair (x0 -> low, x1 -> high) into bf16 hi word + bf16 residual word
__device__ __forceinline__ void bsplit2(float x0, float x1, uint32_t& h, uint32_t& l) {
    h = cvt2(x1, x0);
    l = cvt2(x1 - bhi(h), x0 - blo(h));
}

__device__ __forceinline__ void mma16(float* d, const uint4& a, uint32_t b0, uint32_t b1) {
    asm volatile("mma.sync.aligned.m16n8k16.row.col.f32.bf16.bf16.f32 "
        "{%0,%1,%2,%3}, {%4,%5,%6,%7}, {%8,%9}, {%0,%1,%2,%3};"
        : "+f"(d[0]), "+f"(d[1]), "+f"(d[2]), "+f"(d[3])
        : "r"(a.x), "r"(a.y), "r"(a.z), "r"(a.w), "r"(b0), "r"(b1));
}

// A-fragment address for element (e, c); store hi u32 at p, lo at p+512
__device__ __forceinline__ char* af_addr(char* AF, int nks, int e, int c) {
    int ks = c >> 4, cc = c & 15;
    int reg = ((e >> 3) & 1) | (((cc >> 3) & 1) << 1);
    int lane = ((e & 7) << 2) | ((cc >> 1) & 3);
    return AF + ((e >> 4) * nks + ks) * SEGSZ + lane * 16 + reg * 4;
}

// W fragments: float4 = (bh0, bh1, bl0, bl1) per (ks16, ntile, lane)
__device__ __forceinline__ void build_wfrag(char* WF, const float* __restrict__ Wg,
                                            int CI, int NKS, int KVALID, int t) {
    for (int i = t; i < NKS * 8 * 32; i += 256) {
        int l = i & 31, nt = (i >> 5) & 7, ks = i >> 8;
        int co = nt * 8 + (l >> 2);
        int k0 = ks * 16 + 2 * (l & 3);
        int k2 = k0 + 8;
        float w0 = (k0     < KVALID) ? Wg[co * CI + k0]     : 0.f;
        float w1 = (k0 + 1 < KVALID) ? Wg[co * CI + k0 + 1] : 0.f;
        float w2 = (k2     < KVALID) ? Wg[co * CI + k2]     : 0.f;
        float w3 = (k2 + 1 < KVALID) ? Wg[co * CI + k2 + 1] : 0.f;
        uint32_t bh0, bl0, bh1, bl1;
        bsplit2(w0, w1, bh0, bl0);
        bsplit2(w2, w3, bh1, bl1);
        *(uint4*)(WF + (size_t)i * 16) = make_uint4(bh0, bh1, bl0, bl1);
    }
}

// ---------------- GEMM: warp = m32 x n64, 3-term bf16 split ----------------
template<int NKS>
__device__ __forceinline__ void gemm_bf16(const char* AF, const char* WF,
                                          int w, int l, float acc[2][8][4]) {
#pragma unroll
    for (int mt = 0; mt < 2; mt++)
#pragma unroll
        for (int nt = 0; nt < 8; nt++)
#pragma unroll
            for (int q = 0; q < 4; q++) acc[mt][nt][q] = 0.f;

#pragma unroll
    for (int ks = 0; ks < NKS; ks++) {
        const char* seg0 = AF + ((2 * w)     * NKS + ks) * SEGSZ;
        const char* seg1 = AF + ((2 * w + 1) * NKS + ks) * SEGSZ;
        uint4 ah0 = *(const uint4*)(seg0 +       l * 16);
        uint4 al0 = *(const uint4*)(seg0 + 512 + l * 16);
        uint4 ah1 = *(const uint4*)(seg1 +       l * 16);
        uint4 al1 = *(const uint4*)(seg1 + 512 + l * 16);
#pragma unroll
        for (int nt = 0; nt < 8; nt++) {
            uint4 bv = *(const uint4*)(WF + ((size_t)((ks * 8 + nt) * 32 + l)) * 16);
            mma16(acc[0][nt], ah0, bv.x, bv.y);
            mma16(acc[0][nt], al0, bv.x, bv.y);
            mma16(acc[0][nt], ah0, bv.z, bv.w);
            mma16(acc[1][nt], ah1, bv.x, bv.y);
            mma16(acc[1][nt], al1, bv.x, bv.y);
            mma16(acc[1][nt], ah1, bv.z, bv.w);
        }
    }
}

// ---------------- epilogues ----------------
__device__ __forceinline__ void epi_store(float acc[2][8][4], float* __restrict__ yout,
                                          int tile, int w, int l) {
    float* base = yout + ((size_t)tile * TE + w * 32) * CO;
    int r = l >> 2, j2 = (l & 3) * 2;
#pragma unroll
    for (int mt = 0; mt < 2; mt++)
#pragma unroll
        for (int nt = 0; nt < 8; nt++) {
            int c = nt * 8 + j2;
            *(float2*)&base[(mt * 16 + r)     * CO + c] = make_float2(acc[mt][nt][0], acc[mt][nt][1]);
            *(float2*)&base[(mt * 16 + r + 8) * CO + c] = make_float2(acc[mt][nt][2], acc[mt][nt][3]);
        }
}

__device__ __forceinline__ void epi_stats(float acc[2][8][4], int tile, int w, int l, bool domm) {
#pragma unroll
    for (int nt = 0; nt < 8; nt++)
#pragma unroll
        for (int p = 0; p < 2; p++) {
            float s = 0.f, q = 0.f, mx = -1e30f, mn = 1e30f;
#pragma unroll
            for (int mt = 0; mt < 2; mt++)
#pragma unroll
                for (int hh = 0; hh < 2; hh++) {
                    float v = acc[mt][nt][hh * 2 + p];
                    s += v; q += v * v;
                    mx = fmaxf(mx, v); mn = fminf(mn, v);
                }
#pragma unroll
            for (int o = 4; o <= 16; o <<= 1) {
                s += __shfl_xor_sync(0xffffffffu, s, o);
                q += __shfl_xor_sync(0xffffffffu, q, o);
                if (domm) {
                    mx = fmaxf(mx, __shfl_xor_sync(0xffffffffu, mx, o));
                    mn = fminf(mn, __shfl_xor_sync(0xffffffffu, mn, o));
                }
            }
            if (l < 4) {
                int c = nt * 8 + l * 2 + p;
                size_t slot = (size_t)tile * 8 + w;
                g_psum[slot * CO + c] = s;
                g_psq [slot * CO + c] = q;
                if (domm) {
                    g_mx[slot * CO + c] = mx;   // slot == point index
                    g_mn[slot * CO + c] = mn;
                }
            }
        }
}

// ---------------- edges dtype detection ----------------
__global__ void detect_kernel(const long long* __restrict__ e)
{
    int f = 0;
    for (int i = 0; i < 64; i++)
        if (((unsigned long long)e[i]) >> 32) f = 1;
    g_e32 = f;
}

// ---------------- layer 1: gather + concat + GEMM(K=48) ----------------
__global__ __launch_bounds__(256, 2) void conv1_kernel(
    const float* __restrict__ signal, const void* __restrict__ edges,
    const float* __restrict__ efeat,  const float* __restrict__ W1)
{
    extern __shared__ char sm[];
    char* AF = sm;
    char* WF = sm + AF1_B;
    const int t = threadIdx.x, w = t >> 5, l = t & 31;
    const int e32 = g_e32;

    build_wfrag(WF, W1, 35, KS1, 35, t);
    __syncthreads();

    for (int it = 0; it < TPC; it++) {
        const int tile = blockIdx.x * TPC + it;
        {
            long long ge = (long long)tile * TE + t;
            long long s = e32 ? (long long)((const int*)edges)[ge]
                              : ((const long long*)edges)[ge];
            const float4* row = (const float4*)(signal + s * 32);
#pragma unroll
            for (int m = 0; m < 8; m++) {
                float4 v = row[m];
                uint32_t h01, l01, h23, l23;
                bsplit2(v.x, v.y, h01, l01);
                bsplit2(v.z, v.w, h23, l23);
                char* p = af_addr(AF, KS1, t, 4 * m);
                *(uint32_t*)(p)            = h01;
                *(uint32_t*)(p + 512)      = l01;
                *(uint32_t*)(p + 16)       = h23;
                *(uint32_t*)(p + 512 + 16) = l23;
            }
            const float* fp = efeat + ge * 3;
            uint32_t h01, l01, h23, l23;
            bsplit2(fp[0], fp[1], h01, l01);
            bsplit2(fp[2], 0.f,   h23, l23);
            char* p = af_addr(AF, KS1, t, 32);
            *(uint32_t*)(p)            = h01;
            *(uint32_t*)(p + 512)      = l01;
            *(uint32_t*)(p + 16)       = h23;
            *(uint32_t*)(p + 512 + 16) = l23;
            if (it == 0) {
#pragma unroll
                for (int c = 36; c < 48; c += 2) {
                    char* pz = af_addr(AF, KS1, t, c);
                    *(uint32_t*)(pz)       = 0u;
                    *(uint32_t*)(pz + 512) = 0u;
                }
            }
        }
        __syncthreads();

        float acc[2][8][4];
        gemm_bf16<KS1>(AF, WF, w, l, acc);
        epi_store(acc, g_bufA, tile, w, l);
        epi_stats(acc, tile, w, l, false);
        __syncthreads();
    }
}

// ---------------- layers 2/3: fused norm+lrelu + GEMM(K=64) ----------------
__global__ __launch_bounds__(256, 2) void conv_mid_kernel(int swap, const float* __restrict__ Wg, int mode)
{
    const float* __restrict__ yin = swap ? g_bufB : g_bufA;
    float* __restrict__ yout      = swap ? g_bufA : g_bufB;

    extern __shared__ char sm[];
    char* AF = sm;
    char* WF = sm + AFM_B;
    float* s_sc = (float*)(sm + AFM_B + WFM_B);
    float* s_sh = s_sc + CO;
    const int t = threadIdx.x, w = t >> 5, l = t & 31;
    const int b = (blockIdx.x * TPC) / TPBt;

    build_wfrag(WF, Wg, 64, KSM, 64, t);
    if (t < CO) {
        s_sc[t] = g_scale[b * CO + t];
        s_sh[t] = g_shift[b * CO + t];
    }
    __syncthreads();

    for (int it = 0; it < TPC; it++) {
        const int tile = blockIdx.x * TPC + it;
        const float4* src = (const float4*)(yin + (size_t)tile * TE * CO);
#pragma unroll
        for (int i = 0; i < 16; i++) {
            int f = i * 256 + t;
            float4 v = src[f];
            int e = f >> 4, c0 = (f & 15) * 4;
            float y0, y1, y2, y3;
            y0 = fmaf(v.x, s_sc[c0 + 0], s_sh[c0 + 0]); y0 = y0 >= 0.f ? y0 : 0.1f * y0;
            y1 = fmaf(v.y, s_sc[c0 + 1], s_sh[c0 + 1]); y1 = y1 >= 0.f ? y1 : 0.1f * y1;
            y2 = fmaf(v.z, s_sc[c0 + 2], s_sh[c0 + 2]); y2 = y2 >= 0.f ? y2 : 0.1f * y2;
            y3 = fmaf(v.w, s_sc[c0 + 3], s_sh[c0 + 3]); y3 = y3 >= 0.f ? y3 : 0.1f * y3;
            uint32_t h01, l01, h23, l23;
            bsplit2(y0, y1, h01, l01);
            bsplit2(y2, y3, h23, l23);
            char* p = af_addr(AF, KSM, e, c0);
            *(uint32_t*)(p)            = h01;
            *(uint32_t*)(p + 512)      = l01;
            *(uint32_t*)(p + 16)       = h23;
            *(uint32_t*)(p + 512 + 16) = l23;
        }
        __syncthreads();

        float acc[2][8][4];
        gemm_bf16<KSM>(AF, WF, w, l, acc);
        if (mode == 0) {
            epi_store(acc, yout, tile, w, l);
            epi_stats(acc, tile, w, l, false);
        } else {
            epi_stats(acc, tile, w, l, true);
        }
        __syncthreads();
    }
}

// ---------------- finalize stats -> fused scale/shift ----------------
__global__ void finalize_kernel(const float* __restrict__ gam, const float* __restrict__ bet)
{
    const int b = blockIdx.x >> 6;
    const int c = blockIdx.x & 63;
    __shared__ float sS[256], sQ[256];
    const int t = threadIdx.x;
    float S = 0.f, Q = 0.f;
    const size_t base = (size_t)b * (TPBt * 8);
    for (int i = t; i < TPBt * 8; i += 256) {
        S += g_psum[(base + i) * CO + c];
        Q += g_psq [(base + i) * CO + c];
    }
    sS[t] = S; sQ[t] = Q;
    __syncthreads();
    for (int off = 128; off > 0; off >>= 1) {
        if (t < off) { sS[t] += sS[t + off]; sQ[t] += sQ[t + off]; }
        __syncthreads();
    }
    if (t == 0) {
        float mu  = sS[0] / (float)MCNT;
        float var = sQ[0] / (float)MCNT - mu * mu;
        float rstd = rsqrtf(var + 1e-5f);
        float scl = gam[c] * rstd;
        g_scale[b * CO + c] = scl;
        g_shift[b * CO + c] = bet[c] - mu * scl;
    }
}

// ---------------- final pool: affine + lrelu on max/min ----------------
__global__ __launch_bounds__(256) void pool_kernel(float* __restrict__ out)
{
    const int i = blockIdx.x * 256 + threadIdx.x;   // point*64 + c
    const int p = i >> 6, c = i & 63;
    const int b = p >> 13;
    const float sc = g_scale[b * CO + c];
    const float sh = g_shift[b * CO + c];
    const float v = (sc >= 0.f) ? g_mx[i] : g_mn[i];
    float y = fmaf(v, sc, sh);
    out[i] = y >= 0.f ? y : 0.1f * y;
}

// ---------------- launch ----------------
extern "C" void kernel_launch(void* const* d_in, const int* in_sizes, int n_in,
                              void* d_out, int out_size)
{
    const float* signal = (const float*)d_in[0];
    const void*  edges  = d_in[1];
    const float* efeat  = (const float*)d_in[2];
    const int base = (in_sizes[3] == 1) ? 4 : 3;
    const float* W1 = (const float*)d_in[base + 0];
    const float* g1 = (const float*)d_in[base + 1];
    const float* b1 = (const float*)d_in[base + 2];
    const float* W2 = (const float*)d_in[base + 3];
    const float* g2 = (const float*)d_in[base + 4];
    const float* b2 = (const float*)d_in[base + 5];
    const float* W3 = (const float*)d_in[base + 6];
    const float* g3 = (const float*)d_in[base + 7];
    const float* b3 = (const float*)d_in[base + 8];

    cudaFuncSetAttribute(conv1_kernel,    cudaFuncAttributeMaxDynamicSharedMemorySize, SM1_TOT);
    cudaFuncSetAttribute(conv_mid_kernel, cudaFuncAttributeMaxDynamicSharedMemorySize, SMM_TOT);

    detect_kernel<<<1, 1>>>((const long long*)edges);
    conv1_kernel<<<GRIDC, 256, SM1_TOT>>>(signal, edges, efeat, W1);
    finalize_kernel<<<NB * CO, 256>>>(g1, b1);
    conv_mid_kernel<<<GRIDC, 256, SMM_TOT>>>(0, W2, 0);   // A -> B
    finalize_kernel<<<NB * CO, 256>>>(g2, b2);
    conv_mid_kernel<<<GRIDC, 256, SMM_TOT>>>(1, W3, 1);   // B -> max/min
    finalize_kernel<<<NB * CO, 256>>>(g3, b3);
    pool_kernel<<<NPTS * CO / 256, 256>>>((float*)d_out);
}

// round 14
// speedup vs baseline: 2.4331x; 1.0956x over previous
#include <cuda_runtime.h>
#include <cuda_bf16.h>
#include <cstdint>
#include <math.h>

// ---------------- problem constants ----------------
#define NB    4
#define NN    8192
#define CO    64
#define KKN   32
#define E_TOT (NB*NN*KKN)     // 1048576
#define TE    128             // edges per tile
#define NTIL  (E_TOT/TE)      // 8192
#define TPBt  (NTIL/NB)       // 2048
#define TPC   4
#define GRIDC (NTIL/TPC)      // 2048
#define NPTS  (E_TOT/KKN)     // 32768
#define PPB   (NPTS/NB)       // 8192 points per batch
#define MCNT  (NN*KKN)

#define SEGSZ 1040            // padded A-frag segment (512 hi + 512 lo + 16 pad)
#define KS1   3               // conv1 k16-steps (35 -> 48)
#define KSM   4               // mid k16-steps (64)

#define AF1_B (8*KS1*SEGSZ)               // 24960
#define WF1_B (KS1*8*32*16)               // 12288
#define SM1_TOT (AF1_B + WF1_B)           // 37248
#define AFM_B (8*KSM*SEGSZ)               // 33280
#define WFM_B (KSM*8*32*16)               // 16384
#define SMM_TOT (AFM_B + WFM_B + 512)     // 50176 -> 3 CTA/SM

// ---------------- device scratch ----------------
__device__ float g_bufA[(size_t)E_TOT * CO];   // 268 MB
__device__ float g_bufB[(size_t)E_TOT * CO];   // 268 MB
__device__ float g_psum[(size_t)NPTS * CO];    // per-point partials
__device__ float g_psq [(size_t)NPTS * CO];
__device__ float g_mx  [(size_t)NPTS * CO];
__device__ float g_mn  [(size_t)NPTS * CO];
__device__ float g_scale[NB * CO];
__device__ float g_shift[NB * CO];
__device__ int   g_e32;

// ---------------- bf16 helpers ----------------
__device__ __forceinline__ uint32_t cvt2(float hi_val, float lo_val) {
    uint32_t r;
    asm("cvt.rn.bf16x2.f32 %0, %1, %2;" : "=r"(r) : "f"(hi_val), "f"(lo_val));
    return r;
}
__device__ __forceinline__ float blo(uint32_t p) { return __uint_as_float(p << 16); }
__device__ __forceinline__ float bhi(uint32_t p) { return __uint_as_float(p & 0xffff0000u); }

__device__ __forceinline__ void bsplit2(float x0, float x1, uint32_t& h, uint32_t& l) {
    h = cvt2(x1, x0);
    l = cvt2(x1 - bhi(h), x0 - blo(h));
}

__device__ __forceinline__ void mma16(float* d, const uint4& a, uint32_t b0, uint32_t b1) {
    asm volatile("mma.sync.aligned.m16n8k16.row.col.f32.bf16.bf16.f32 "
        "{%0,%1,%2,%3}, {%4,%5,%6,%7}, {%8,%9}, {%0,%1,%2,%3};"
        : "+f"(d[0]), "+f"(d[1]), "+f"(d[2]), "+f"(d[3])
        : "r"(a.x), "r"(a.y), "r"(a.z), "r"(a.w), "r"(b0), "r"(b1));
}

// A-fragment address for element (e, c); hi u32 at p, lo at p+512
__device__ __forceinline__ char* af_addr(char* AF, int nks, int e, int c) {
    int ks = c >> 4, cc = c & 15;
    int reg = ((e >> 3) & 1) | (((cc >> 3) & 1) << 1);
    int lane = ((e & 7) << 2) | ((cc >> 1) & 3);
    return AF + ((e >> 4) * nks + ks) * SEGSZ + lane * 16 + reg * 4;
}

// W fragments: float4 = (bh0, bh1, bl0, bl1) per (ks16, ntile, lane)
__device__ __forceinline__ void build_wfrag(char* WF, const float* __restrict__ Wg,
                                            int CI, int NKS, int KVALID, int t) {
    for (int i = t; i < NKS * 8 * 32; i += 256) {
        int l = i & 31, nt = (i >> 5) & 7, ks = i >> 8;
        int co = nt * 8 + (l >> 2);
        int k0 = ks * 16 + 2 * (l & 3);
        int k2 = k0 + 8;
        float w0 = (k0     < KVALID) ? Wg[co * CI + k0]     : 0.f;
        float w1 = (k0 + 1 < KVALID) ? Wg[co * CI + k0 + 1] : 0.f;
        float w2 = (k2     < KVALID) ? Wg[co * CI + k2]     : 0.f;
        float w3 = (k2 + 1 < KVALID) ? Wg[co * CI + k2 + 1] : 0.f;
        uint32_t bh0, bl0, bh1, bl1;
        bsplit2(w0, w1, bh0, bl0);
        bsplit2(w2, w3, bh1, bl1);
        *(uint4*)(WF + (size_t)i * 16) = make_uint4(bh0, bh1, bl0, bl1);
    }
}

// ---------------- GEMM: warp = m32 x n32 (wm 0..3, wn 0..1), 3-term bf16 split ----------------
template<int NKS>
__device__ __forceinline__ void gemm_bf16(const char* AF, const char* WF,
                                          int wm, int wn, int l, float acc[2][4][4]) {
#pragma unroll
    for (int mt = 0; mt < 2; mt++)
#pragma unroll
        for (int nt = 0; nt < 4; nt++)
#pragma unroll
            for (int q = 0; q < 4; q++) acc[mt][nt][q] = 0.f;

#pragma unroll
    for (int ks = 0; ks < NKS; ks++) {
        const char* seg0 = AF + ((2 * wm)     * NKS + ks) * SEGSZ;
        const char* seg1 = AF + ((2 * wm + 1) * NKS + ks) * SEGSZ;
        uint4 ah0 = *(const uint4*)(seg0 +       l * 16);
        uint4 al0 = *(const uint4*)(seg0 + 512 + l * 16);
        uint4 ah1 = *(const uint4*)(seg1 +       l * 16);
        uint4 al1 = *(const uint4*)(seg1 + 512 + l * 16);
#pragma unroll
        for (int nt = 0; nt < 4; nt++) {
            int ntg = wn * 4 + nt;
            uint4 bv = *(const uint4*)(WF + ((size_t)((ks * 8 + ntg) * 32 + l)) * 16);
            mma16(acc[0][nt], ah0, bv.x, bv.y);
            mma16(acc[0][nt], al0, bv.x, bv.y);
            mma16(acc[0][nt], ah0, bv.z, bv.w);
            mma16(acc[1][nt], ah1, bv.x, bv.y);
            mma16(acc[1][nt], al1, bv.x, bv.y);
            mma16(acc[1][nt], ah1, bv.z, bv.w);
        }
    }
}

// ---------------- epilogues ----------------
__device__ __forceinline__ void epi_store(float acc[2][4][4], float* __restrict__ yout,
                                          int tile, int wm, int wn, int l) {
    float* base = yout + ((size_t)tile * TE + wm * 32) * CO;
    int r = l >> 2, j2 = (l & 3) * 2;
#pragma unroll
    for (int mt = 0; mt < 2; mt++)
#pragma unroll
        for (int nt = 0; nt < 4; nt++) {
            int c = wn * 32 + nt * 8 + j2;
            *(float2*)&base[(mt * 16 + r)     * CO + c] = make_float2(acc[mt][nt][0], acc[mt][nt][1]);
            *(float2*)&base[(mt * 16 + r + 8) * CO + c] = make_float2(acc[mt][nt][2], acc[mt][nt][3]);
        }
}

__device__ __forceinline__ void epi_stats(float acc[2][4][4], int tile, int wm, int wn,
                                          int l, bool domm) {
    const size_t pt = (size_t)tile * 4 + wm;   // point index
#pragma unroll
    for (int nt = 0; nt < 4; nt++)
#pragma unroll
        for (int p = 0; p < 2; p++) {
            float s = 0.f, q = 0.f, mx = -1e30f, mn = 1e30f;
#pragma unroll
            for (int mt = 0; mt < 2; mt++)
#pragma unroll
                for (int hh = 0; hh < 2; hh++) {
                    float v = acc[mt][nt][hh * 2 + p];
                    s += v; q += v * v;
                    mx = fmaxf(mx, v); mn = fminf(mn, v);
                }
#pragma unroll
            for (int o = 4; o <= 16; o <<= 1) {
                s += __shfl_xor_sync(0xffffffffu, s, o);
                q += __shfl_xor_sync(0xffffffffu, q, o);
                if (domm) {
                    mx = fmaxf(mx, __shfl_xor_sync(0xffffffffu, mx, o));
                    mn = fminf(mn, __shfl_xor_sync(0xffffffffu, mn, o));
                }
            }
            if (l < 4) {
                int c = wn * 32 + nt * 8 + l * 2 + p;
                g_psum[pt * CO + c] = s;
                g_psq [pt * CO + c] = q;
                if (domm) {
                    g_mx[pt * CO + c] = mx;
                    g_mn[pt * CO + c] = mn;
                }
            }
        }
}

// ---------------- edges dtype detection ----------------
__global__ void detect_kernel(const long long* __restrict__ e)
{
    int f = 0;
    for (int i = 0; i < 64; i++)
        if (((unsigned long long)e[i]) >> 32) f = 1;
    g_e32 = f;
}

// ---------------- layer 1: gather + concat + GEMM(K=48) ----------------
__global__ __launch_bounds__(256, 3) void conv1_kernel(
    const float* __restrict__ signal, const void* __restrict__ edges,
    const float* __restrict__ efeat,  const float* __restrict__ W1)
{
    extern __shared__ char sm[];
    char* AF = sm;
    char* WF = sm + AF1_B;
    const int t = threadIdx.x, w = t >> 5, l = t & 31;
    const int wm = w & 3, wn = w >> 2;
    const int e32 = g_e32;

    build_wfrag(WF, W1, 35, KS1, 35, t);
    __syncthreads();

    const int el = t >> 1, h = t & 1;

    for (int it = 0; it < TPC; it++) {
        const int tile = blockIdx.x * TPC + it;
        {
            long long ge = (long long)tile * TE + el;
            long long s = e32 ? (long long)((const int*)edges)[ge]
                              : ((const long long*)edges)[ge];
            const float4* row = (const float4*)(signal + s * 32) + h * 4;
#pragma unroll
            for (int m = 0; m < 4; m++) {
                float4 v = row[m];
                uint32_t h01, l01, h23, l23;
                bsplit2(v.x, v.y, h01, l01);
                bsplit2(v.z, v.w, h23, l23);
                char* p = af_addr(AF, KS1, el, h * 16 + 4 * m);
                *(uint32_t*)(p)            = h01;
                *(uint32_t*)(p + 512)      = l01;
                *(uint32_t*)(p + 16)       = h23;
                *(uint32_t*)(p + 512 + 16) = l23;
            }
            if (h == 1) {
                const float* fp = efeat + ge * 3;
                uint32_t h01, l01, h23, l23;
                bsplit2(fp[0], fp[1], h01, l01);
                bsplit2(fp[2], 0.f,   h23, l23);
                char* p = af_addr(AF, KS1, el, 32);
                *(uint32_t*)(p)            = h01;
                *(uint32_t*)(p + 512)      = l01;
                *(uint32_t*)(p + 16)       = h23;
                *(uint32_t*)(p + 512 + 16) = l23;
            } else if (it == 0) {
#pragma unroll
                for (int c = 36; c < 48; c += 2) {
                    char* pz = af_addr(AF, KS1, el, c);
                    *(uint32_t*)(pz)       = 0u;
                    *(uint32_t*)(pz + 512) = 0u;
                }
            }
        }
        __syncthreads();

        float acc[2][4][4];
        gemm_bf16<KS1>(AF, WF, wm, wn, l, acc);
        epi_store(acc, g_bufA, tile, wm, wn, l);
        epi_stats(acc, tile, wm, wn, l, false);
        __syncthreads();
    }
}

// ---------------- layers 2/3: fused norm+lrelu + GEMM(K=64) ----------------
__global__ __launch_bounds__(256, 3) void conv_mid_kernel(int swap, const float* __restrict__ Wg, int mode)
{
    const float* __restrict__ yin = swap ? g_bufB : g_bufA;
    float* __restrict__ yout      = swap ? g_bufA : g_bufB;

    extern __shared__ char sm[];
    char* AF = sm;
    char* WF = sm + AFM_B;
    float* s_sc = (float*)(sm + AFM_B + WFM_B);
    float* s_sh = s_sc + CO;
    const int t = threadIdx.x, w = t >> 5, l = t & 31;
    const int wm = w & 3, wn = w >> 2;
    const int b = (blockIdx.x * TPC) / TPBt;

    build_wfrag(WF, Wg, 64, KSM, 64, t);
    if (t < CO) {
        s_sc[t] = g_scale[b * CO + t];
        s_sh[t] = g_shift[b * CO + t];
    }
    __syncthreads();

    for (int it = 0; it < TPC; it++) {
        const int tile = blockIdx.x * TPC + it;
        const float4* src = (const float4*)(yin + (size_t)tile * TE * CO);
#pragma unroll
        for (int i = 0; i < 8; i++) {
            int f = i * 256 + t;          // float4 index 0..2047
            float4 v = src[f];
            int e = f >> 4, c0 = (f & 15) * 4;
            float y0, y1, y2, y3;
            y0 = fmaf(v.x, s_sc[c0 + 0], s_sh[c0 + 0]); y0 = y0 >= 0.f ? y0 : 0.1f * y0;
            y1 = fmaf(v.y, s_sc[c0 + 1], s_sh[c0 + 1]); y1 = y1 >= 0.f ? y1 : 0.1f * y1;
            y2 = fmaf(v.z, s_sc[c0 + 2], s_sh[c0 + 2]); y2 = y2 >= 0.f ? y2 : 0.1f * y2;
            y3 = fmaf(v.w, s_sc[c0 + 3], s_sh[c0 + 3]); y3 = y3 >= 0.f ? y3 : 0.1f * y3;
            uint32_t h01, l01, h23, l23;
            bsplit2(y0, y1, h01, l01);
            bsplit2(y2, y3, h23, l23);
            char* p = af_addr(AF, KSM, e, c0);
            *(uint32_t*)(p)            = h01;
            *(uint32_t*)(p + 512)      = l01;
            *(uint32_t*)(p + 16)       = h23;
            *(uint32_t*)(p + 512 + 16) = l23;
        }
        __syncthreads();

        float acc[2][4][4];
        gemm_bf16<KSM>(AF, WF, wm, wn, l, acc);
        if (mode == 0) {
            epi_store(acc, yout, tile, wm, wn, l);
            epi_stats(acc, tile, wm, wn, l, false);
        } else {
            epi_stats(acc, tile, wm, wn, l, true);
        }
        __syncthreads();
    }
}

// ---------------- finalize stats -> fused scale/shift ----------------
__global__ void finalize_kernel(const float* __restrict__ gam, const float* __restrict__ bet)
{
    const int b = blockIdx.x >> 6;
    const int c = blockIdx.x & 63;
    __shared__ float sS[256], sQ[256];
    const int t = threadIdx.x;
    float S = 0.f, Q = 0.f;
    const size_t base = (size_t)b * PPB;
    for (int i = t; i < PPB; i += 256) {
        S += g_psum[(base + i) * CO + c];
        Q += g_psq [(base + i) * CO + c];
    }
    sS[t] = S; sQ[t] = Q;
    __syncthreads();
    for (int off = 128; off > 0; off >>= 1) {
        if (t < off) { sS[t] += sS[t + off]; sQ[t] += sQ[t + off]; }
        __syncthreads();
    }
    if (t == 0) {
        float mu  = sS[0] / (float)MCNT;
        float var = sQ[0] / (float)MCNT - mu * mu;
        float rstd = rsqrtf(var + 1e-5f);
        float scl = gam[c] * rstd;
        g_scale[b * CO + c] = scl;
        g_shift[b * CO + c] = bet[c] - mu * scl;
    }
}

// ---------------- final pool: affine + lrelu on max/min ----------------
__global__ __launch_bounds__(256) void pool_kernel(float* __restrict__ out)
{
    const int i = blockIdx.x * 256 + threadIdx.x;   // point*64 + c
    const int p = i >> 6, c = i & 63;
    const int b = p >> 13;
    const float sc = g_scale[b * CO + c];
    const float sh = g_shift[b * CO + c];
    const float v = (sc >= 0.f) ? g_mx[i] : g_mn[i];
    float y = fmaf(v, sc, sh);
    out[i] = y >= 0.f ? y : 0.1f * y;
}

// ---------------- launch ----------------
extern "C" void kernel_launch(void* const* d_in, const int* in_sizes, int n_in,
                              void* d_out, int out_size)
{
    const float* signal = (const float*)d_in[0];
    const void*  edges  = d_in[1];
    const float* efeat  = (const float*)d_in[2];
    const int base = (in_sizes[3] == 1) ? 4 : 3;
    const float* W1 = (const float*)d_in[base + 0];
    const float* g1 = (const float*)d_in[base + 1];
    const float* b1 = (const float*)d_in[base + 2];
    const float* W2 = (const float*)d_in[base + 3];
    const float* g2 = (const float*)d_in[base + 4];
    const float* b2 = (const float*)d_in[base + 5];
    const float* W3 = (const float*)d_in[base + 6];
    const float* g3 = (const float*)d_in[base + 7];
    const float* b3 = (const float*)d_in[base + 8];

    cudaFuncSetAttribute(conv1_kernel,    cudaFuncAttributeMaxDynamicSharedMemorySize, SM1_TOT);
    cudaFuncSetAttribute(conv_mid_kernel, cudaFuncAttributeMaxDynamicSharedMemorySize, SMM_TOT);

    detect_kernel<<<1, 1>>>((const long long*)edges);
    conv1_kernel<<<GRIDC, 256, SM1_TOT>>>(signal, edges, efeat, W1);
    finalize_kernel<<<NB * CO, 256>>>(g1, b1);
    conv_mid_kernel<<<GRIDC, 256, SMM_TOT>>>(0, W2, 0);   // A -> B
    finalize_kernel<<<NB * CO, 256>>>(g2, b2);
    conv_mid_kernel<<<GRIDC, 256, SMM_TOT>>>(1, W3, 1);   // B -> max/min
    finalize_kernel<<<NB * CO, 256>>>(g3, b3);
    pool_kernel<<<NPTS * CO / 256, 256>>>((float*)d_out);
}